// round 12
// baseline (speedup 1.0000x reference)
#include <cuda_runtime.h>
#include <cuda_fp16.h>
#include <math.h>
#include <stdint.h>

#define T_TOK 2048
#define H_DIM 1024
#define E_NUM 8
#define I_DIM 2048

// ---------------- device scratch ----------------
__device__ int    g_count[E_NUM];
__device__ int    g_tok[E_NUM][T_TOK];
__device__ float  g_wt[E_NUM][T_TOK];
__device__ int    g_slot[T_TOK][2];
__device__ __half g_x16[(size_t)E_NUM * T_TOK * H_DIM];  // 32 MB gathered fp16 hs
__device__ __half g_act[(size_t)E_NUM * T_TOK * I_DIM];  // 64 MB fp16
__device__ float  g_y[(size_t)E_NUM * T_TOK * H_DIM];    // 64 MB

// ---------------- helpers ----------------
__device__ __forceinline__ uint32_t f2h2(float lo, float hi) {
    __half2 h;
    h.x = __float2half_rn(lo);
    h.y = __float2half_rn(hi);
    return *reinterpret_cast<uint32_t*>(&h);
}
__device__ __forceinline__ void mma_f16(float* c, const uint32_t* a, const uint32_t* b) {
    asm volatile(
        "mma.sync.aligned.m16n8k16.row.col.f32.f16.f16.f32 "
        "{%0,%1,%2,%3}, {%4,%5,%6,%7}, {%8,%9}, {%0,%1,%2,%3};"
        : "+f"(c[0]), "+f"(c[1]), "+f"(c[2]), "+f"(c[3])
        : "r"(a[0]), "r"(a[1]), "r"(a[2]), "r"(a[3]), "r"(b[0]), "r"(b[1]));
}
#define BAR_SYNC(id, cnt)   asm volatile("bar.sync %0, %1;"   :: "r"(id), "r"(cnt) : "memory")
#define BAR_ARRIVE(id, cnt) asm volatile("bar.arrive %0, %1;" :: "r"(id), "r"(cnt) : "memory")

// ---------------- small kernels ----------------
__global__ void zero_counts_kernel() {
    if (threadIdx.x < E_NUM) g_count[threadIdx.x] = 0;
}

__global__ void router_kernel(const float* __restrict__ hs, const float* __restrict__ gw) {
    int t = blockIdx.x;
    const float* x = hs + (size_t)t * H_DIM;
    float acc[E_NUM];
#pragma unroll
    for (int e = 0; e < E_NUM; e++) acc[e] = 0.f;
    for (int j = threadIdx.x; j < H_DIM; j += blockDim.x) {
        float xv = x[j];
        const float4* grow = reinterpret_cast<const float4*>(gw + (size_t)j * E_NUM);
        float4 g0 = grow[0], g1 = grow[1];
        acc[0] += xv * g0.x; acc[1] += xv * g0.y; acc[2] += xv * g0.z; acc[3] += xv * g0.w;
        acc[4] += xv * g1.x; acc[5] += xv * g1.y; acc[6] += xv * g1.z; acc[7] += xv * g1.w;
    }
#pragma unroll
    for (int off = 16; off > 0; off >>= 1)
#pragma unroll
        for (int e = 0; e < E_NUM; e++)
            acc[e] += __shfl_xor_sync(0xffffffffu, acc[e], off);
    __shared__ float s[4][E_NUM];
    int warp = threadIdx.x >> 5, lane = threadIdx.x & 31;
    if (lane == 0)
#pragma unroll
        for (int e = 0; e < E_NUM; e++) s[warp][e] = acc[e];
    __syncthreads();
    if (threadIdx.x == 0) {
        float l[E_NUM];
#pragma unroll
        for (int e = 0; e < E_NUM; e++)
            l[e] = tanhf((s[0][e] + s[1][e] + s[2][e] + s[3][e]) * (1.0f / 30.0f));
        int i0 = 0;
#pragma unroll
        for (int e = 1; e < E_NUM; e++) if (l[e] > l[i0]) i0 = e;
        int i1 = (i0 == 0) ? 1 : 0;
#pragma unroll
        for (int e = 0; e < E_NUM; e++) if (e != i0 && l[e] > l[i1]) i1 = e;
        float d  = l[i1] - l[i0];
        float ed = expf(d);
        float inv = 1.0f / (1.0f + ed);
        float p0 = inv, p1 = ed * inv;
        int p = atomicAdd(&g_count[i0], 1);
        g_tok[i0][p] = t; g_wt[i0][p] = p0; g_slot[t][0] = i0 * T_TOK + p;
        p = atomicAdd(&g_count[i1], 1);
        g_tok[i1][p] = t; g_wt[i1][p] = p1; g_slot[t][1] = i1 * T_TOK + p;
    }
}

// gather hs rows into fp16 slot-order buffer (per expert)
__global__ __launch_bounds__(256) void gather_x_kernel(const float* __restrict__ hs) {
    int e = blockIdx.x;
    int count = g_count[e];
    int s = blockIdx.y * 8 + (threadIdx.x >> 5);
    if (s >= count) return;
    int lane = threadIdx.x & 31;
    int tok = g_tok[e][s];
    const float4* src = reinterpret_cast<const float4*>(hs + (size_t)tok * H_DIM);
    uint2* dst = reinterpret_cast<uint2*>(g_x16 + ((size_t)e * T_TOK + s) * H_DIM);
#pragma unroll
    for (int i = 0; i < 8; ++i) {
        float4 v = src[lane + i * 32];
        dst[lane + i * 32] = make_uint2(f2h2(v.x, v.y), f2h2(v.z, v.w));
    }
}

__device__ __forceinline__ float gelu_tanh(float g) {
    float c = 0.7978845608028654f * (g + 0.044715f * g * g * g);
    return 0.5f * g * (1.0f + tanhf(c));
}

// ===== fragment math: fp16 m16n8k16, warp tile 64x32, 16 warps (2m x 8n) =====
#define GX_MMA(s)                                                                     \
    {                                                                                 \
        const uint32_t* As = sm32 + (s) * 6144;                                       \
        const uint32_t* Bs = As + 2048;                                               \
        const int kl = lane & 3, dn = lane >> 2;                                      \
        _Pragma("unroll")                                                             \
        for (int ks = 0; ks < 2; ++ks) {                                              \
            uint4 af[4];                                                              \
            _Pragma("unroll")                                                         \
            for (int mt = 0; mt < 4; ++mt)                                            \
                af[mt] = *reinterpret_cast<const uint4*>(                             \
                    As + ((ks * 8 + wm * 4 + mt) * 32 + lane) * 4);                   \
            uint2 bf[4];                                                              \
            _Pragma("unroll")                                                         \
            for (int nt = 0; nt < 4; ++nt) {                                          \
                int pn = (wn * 32 + nt * 8 + dn) ^ (kl << 3);                         \
                bf[nt].x = Bs[(ks * 8 + kl) * 256 + pn];                              \
                bf[nt].y = Bs[(ks * 8 + kl + 4) * 256 + pn];                          \
            }                                                                         \
            _Pragma("unroll")                                                         \
            for (int mt = 0; mt < 4; ++mt)                                            \
                _Pragma("unroll")                                                     \
                for (int nt = 0; nt < 4; ++nt)                                        \
                    mma_f16(acc[mt][nt], (const uint32_t*)&af[mt], (const uint32_t*)&bf[nt]); \
        }                                                                             \
    }

// A store mapping for a 4-k group at (m, kq)
#define A_STORE_WORDS(As, m, kq, w0, w1)                                              \
    {                                                                                 \
        int kin = (kq) & 15, ks = (kq) >> 4;                                          \
        int c = (kin >> 1) & 3;                                                       \
        int reg = ((kin & 8) >> 2) + (((m) & 8) >> 3);                                \
        int lane0 = (((m) & 7) << 2) + c;                                             \
        int base = ((ks * 8 + ((m) >> 4)) * 32);                                      \
        (As)[(base + lane0) * 4 + reg] = (w0);                                        \
        (As)[(base + lane0 + 1) * 4 + reg] = (w1);                                    \
    }

// ============================================================================
// GEMM1 (monolithic, as R11): act_fp16 = gelu(X@wg)*(X@wu); A now from g_x16.
// CTA M=128 x Nphys=256, 512 thr, kb=32, 3-stage, 1 sync/chunk.
// ============================================================================
__global__ __launch_bounds__(512, 1)
void gemm1_kernel(const float* __restrict__ wg,
                  const float* __restrict__ wu) {
    const int e = blockIdx.y;
    const int count = g_count[e];
    const int m0 = blockIdx.z * 128;
    if (m0 >= count) return;
    const int n0 = blockIdx.x * 128;

    extern __shared__ uint32_t sm32[];

    const int tid = threadIdx.x, wid = tid >> 5, lane = tid & 31;
    const int wm = wid & 1, wn = wid >> 1;

    const __half* xp  = g_x16 + (size_t)e * T_TOK * H_DIM;
    const float*  wgp = wg + (size_t)e * H_DIM * I_DIM + n0;
    const float*  wup = wu + (size_t)e * H_DIM * I_DIM + n0;

    float acc[4][4][4];
#pragma unroll
    for (int i = 0; i < 4; i++)
#pragma unroll
        for (int j = 0; j < 4; j++)
#pragma unroll
            for (int q = 0; q < 4; q++) acc[i][j][q] = 0.f;

    uint2 rAw[2];
    uint4 rBw[2];

#define G1_LOAD(k0)                                                                   \
    {                                                                                 \
        _Pragma("unroll")                                                             \
        for (int it = 0; it < 2; ++it) {                                              \
            int f = tid + it * 512;                                                   \
            int m = f >> 3, kq = (f & 7) << 2;                                        \
            int gp = m0 + m;                                                          \
            rAw[it] = (gp < count)                                                    \
                ? *reinterpret_cast<const uint2*>(xp + (size_t)gp * H_DIM + (k0) + kq) \
                : make_uint2(0u, 0u);                                                 \
        }                                                                             \
        _Pragma("unroll")                                                             \
        for (int it = 0; it < 2; ++it) {                                              \
            int f = tid + it * 512;                                                   \
            int n4 = f & 63, k2 = f >> 6;                                             \
            int blk = n4 >> 1;                                                        \
            const float* bsrc = (blk & 1) ? wup : wgp;                                \
            int srcoff = (blk >> 1) * 8 + (n4 & 1) * 4;                               \
            float4 r0 = *reinterpret_cast<const float4*>(                             \
                bsrc + (size_t)((k0) + 2 * k2) * I_DIM + srcoff);                     \
            float4 r1 = *reinterpret_cast<const float4*>(                             \
                bsrc + (size_t)((k0) + 2 * k2 + 1) * I_DIM + srcoff);                 \
            rBw[it].x = f2h2(r0.x, r1.x);                                             \
            rBw[it].y = f2h2(r0.y, r1.y);                                             \
            rBw[it].z = f2h2(r0.z, r1.z);                                             \
            rBw[it].w = f2h2(r0.w, r1.w);                                             \
        }                                                                             \
    }

#define G1_STORE(s)                                                                   \
    {                                                                                 \
        uint32_t* As = sm32 + (s) * 6144;                                             \
        uint32_t* Bs = As + 2048;                                                     \
        _Pragma("unroll")                                                             \
        for (int it = 0; it < 2; ++it) {                                              \
            int f = tid + it * 512;                                                   \
            int m = f >> 3, kq = (f & 7) << 2;                                        \
            A_STORE_WORDS(As, m, kq, rAw[it].x, rAw[it].y);                           \
        }                                                                             \
        _Pragma("unroll")                                                             \
        for (int it = 0; it < 2; ++it) {                                              \
            int f = tid + it * 512;                                                   \
            int n4 = f & 63, k2 = f >> 6;                                             \
            int pn4 = n4 ^ ((k2 & 3) << 1);                                           \
            *reinterpret_cast<uint4*>(Bs + k2 * 256 + pn4 * 4) = rBw[it];             \
        }                                                                             \
    }

    const int NC = H_DIM / 32;   // 32
    G1_LOAD(0);
    G1_STORE(0);
    G1_LOAD(32);
    __syncthreads();
    {
        int cs = 0;
        for (int c = 0; c < NC; ++c) {
            int st = (cs == 2) ? 0 : cs + 1;
            if (c + 1 < NC) G1_STORE(st);
            if (c + 2 < NC) G1_LOAD((c + 2) * 32);
            GX_MMA(cs);
            __syncthreads();
            cs = st;
        }
    }

    // ---- epilogue: (acc[mt][2j], acc[mt][2j+1]) = (g,u); write fp16 ----
#pragma unroll
    for (int mt = 0; mt < 4; ++mt) {
        int row_base = wm * 64 + mt * 16 + (lane >> 2);
#pragma unroll
        for (int h = 0; h < 2; ++h) {
            int gpos = m0 + row_base + h * 8;
            if (gpos >= count) continue;
            __half* dst = g_act + ((size_t)e * T_TOK + gpos) * I_DIM + n0;
#pragma unroll
            for (int j = 0; j < 2; ++j) {
                int col = (2 * wn + j) * 8 + (lane & 3) * 2;
                uint32_t w = f2h2(
                    gelu_tanh(acc[mt][2 * j][2 * h])     * acc[mt][2 * j + 1][2 * h],
                    gelu_tanh(acc[mt][2 * j][2 * h + 1]) * acc[mt][2 * j + 1][2 * h + 1]);
                *reinterpret_cast<uint32_t*>(dst + col) = w;
            }
        }
    }
#undef G1_LOAD
#undef G1_STORE
}

// ============================================================================
// GEMM2 (warp-specialized): y = weight * (act_fp16 @ wd).
// 576 thr = 16 consumer warps (64x32 tiles) + 2 producer warps.
// 3 stages, named barriers: FULL ids 1..3, EMPTY ids 4..6 (count 576).
// ============================================================================
#define NTHR2 576
__global__ __launch_bounds__(NTHR2, 1)
void gemm2_kernel(const float* __restrict__ wd) {
    const int e = blockIdx.y;
    const int count = g_count[e];
    const int m0 = blockIdx.z * 128;
    if (m0 >= count) return;
    const int n0 = blockIdx.x * 256;

    extern __shared__ uint32_t sm32[];

    const int tid = threadIdx.x, wid = tid >> 5, lane = tid & 31;
    const int NC = I_DIM / 32;   // 64

    if (wid < 16) {
        // ---------------- consumers ----------------
        const int wm = wid & 1, wn = wid >> 1;
        float acc[4][4][4];
#pragma unroll
        for (int i = 0; i < 4; i++)
#pragma unroll
            for (int j = 0; j < 4; j++)
#pragma unroll
                for (int q = 0; q < 4; q++) acc[i][j][q] = 0.f;

        for (int c = 0; c < NC; ++c) {
            int s = c % 3;
            BAR_SYNC(1 + s, NTHR2);     // wait stage full
            GX_MMA(s);
            BAR_ARRIVE(4 + s, NTHR2);   // release stage
        }

        // epilogue: scale by combine weight, write slot buffer
#pragma unroll
        for (int mt = 0; mt < 4; ++mt) {
            int row_base = wm * 64 + mt * 16 + (lane >> 2);
#pragma unroll
            for (int h = 0; h < 2; ++h) {
                int gpos = m0 + row_base + h * 8;
                if (gpos >= count) continue;
                float w = g_wt[e][gpos];
                float* dst = g_y + ((size_t)e * T_TOK + gpos) * H_DIM + n0;
#pragma unroll
                for (int nt = 0; nt < 4; ++nt) {
                    int col = wn * 32 + nt * 8 + (lane & 3) * 2;
                    float2 o;
                    o.x = w * acc[mt][nt][2 * h];
                    o.y = w * acc[mt][nt][2 * h + 1];
                    *reinterpret_cast<float2*>(dst + col) = o;
                }
            }
        }
    } else {
        // ---------------- producers (64 threads) ----------------
        const int ptid = tid - 512;
        const __half* actp = g_act + (size_t)e * T_TOK * I_DIM;
        const float*  wdp  = wd + (size_t)e * I_DIM * H_DIM + n0;

        for (int c = 0; c < NC; ++c) {
            int s = c % 3;
            const int k0 = c * 32;
            if (c >= 3) BAR_SYNC(4 + s, NTHR2);   // wait consumers done with s
            uint32_t* As = sm32 + s * 6144;
            uint32_t* Bs = As + 2048;

            uint2 a_[16];
#pragma unroll
            for (int it = 0; it < 16; ++it) {
                int f = ptid + it * 64;
                int m = f >> 3, kq = (f & 7) << 2;
                int gp = m0 + m;
                a_[it] = (gp < count)
                    ? *reinterpret_cast<const uint2*>(actp + (size_t)gp * I_DIM + k0 + kq)
                    : make_uint2(0u, 0u);
            }
#pragma unroll
            for (int hb = 0; hb < 2; ++hb) {
                uint4 b_[8];
#pragma unroll
                for (int it = 0; it < 8; ++it) {
                    int f = ptid + (hb * 8 + it) * 64;
                    int n4 = f & 63, k2 = f >> 6;
                    float4 r0 = *reinterpret_cast<const float4*>(
                        wdp + (size_t)(k0 + 2 * k2) * H_DIM + n4 * 4);
                    float4 r1 = *reinterpret_cast<const float4*>(
                        wdp + (size_t)(k0 + 2 * k2 + 1) * H_DIM + n4 * 4);
                    b_[it] = make_uint4(f2h2(r0.x, r1.x), f2h2(r0.y, r1.y),
                                        f2h2(r0.z, r1.z), f2h2(r0.w, r1.w));
                }
#pragma unroll
                for (int it = 0; it < 8; ++it) {
                    int f = ptid + (hb * 8 + it) * 64;
                    int n4 = f & 63, k2 = f >> 6;
                    int pn4 = n4 ^ ((k2 & 3) << 1);
                    *reinterpret_cast<uint4*>(Bs + k2 * 256 + pn4 * 4) = b_[it];
                }
            }
#pragma unroll
            for (int it = 0; it < 16; ++it) {
                int f = ptid + it * 64;
                int m = f >> 3, kq = (f & 7) << 2;
                A_STORE_WORDS(As, m, kq, a_[it].x, a_[it].y);
            }
            BAR_ARRIVE(1 + s, NTHR2);             // stage full
        }
    }
}

// ---------------- combine: out[t] = y[slot0] + y[slot1] ----------------
__global__ __launch_bounds__(256) void combine_kernel(float* __restrict__ out) {
    int t = blockIdx.x;
    int s0 = g_slot[t][0], s1 = g_slot[t][1];
    const float4* y0 = reinterpret_cast<const float4*>(g_y + (size_t)s0 * H_DIM);
    const float4* y1 = reinterpret_cast<const float4*>(g_y + (size_t)s1 * H_DIM);
    float4* o = reinterpret_cast<float4*>(out + (size_t)t * H_DIM);
    int c = threadIdx.x;
    float4 a = y0[c], b = y1[c];
    o[c] = make_float4(a.x + b.x, a.y + b.y, a.z + b.z, a.w + b.w);
}

// ---------------- launch ----------------
extern "C" void kernel_launch(void* const* d_in, const int* in_sizes, int n_in,
                              void* d_out, int out_size) {
    const float* hs = (const float*)d_in[0];   // [T, H]
    const float* gw = (const float*)d_in[1];   // [H, E]
    const float* wg = (const float*)d_in[2];   // [E, H, I]
    const float* wu = (const float*)d_in[3];   // [E, H, I]
    const float* wd = (const float*)d_in[4];   // [E, I, H]
    float* out = (float*)d_out;                // [T, H]

    static bool attr_done = false;
    if (!attr_done) {
        cudaFuncSetAttribute(gemm1_kernel, cudaFuncAttributeMaxDynamicSharedMemorySize, 73728);
        cudaFuncSetAttribute(gemm2_kernel, cudaFuncAttributeMaxDynamicSharedMemorySize, 73728);
        attr_done = true;
    }

    zero_counts_kernel<<<1, 32>>>();
    router_kernel<<<T_TOK, 128>>>(hs, gw);
    gather_x_kernel<<<dim3(E_NUM, T_TOK / 8), 256>>>(hs);

    dim3 g1(I_DIM / 128, E_NUM, T_TOK / 128);   // (16, 8, 16)
    gemm1_kernel<<<g1, 512, 73728>>>(wg, wu);

    dim3 g2(H_DIM / 256, E_NUM, T_TOK / 128);   // (4, 8, 16)
    gemm2_kernel<<<g2, NTHR2, 73728>>>(wd);

    combine_kernel<<<T_TOK, 256>>>(out);
}

// round 13
// speedup vs baseline: 1.1633x; 1.1633x over previous
#include <cuda_runtime.h>
#include <cuda_fp16.h>
#include <math.h>
#include <stdint.h>

#define T_TOK 2048
#define H_DIM 1024
#define E_NUM 8
#define I_DIM 2048

// ---------------- device scratch ----------------
__device__ int    g_count[E_NUM];
__device__ int    g_tok[E_NUM][T_TOK];
__device__ float  g_wt[E_NUM][T_TOK];
__device__ int    g_slot[T_TOK][2];
__device__ __half g_x16[(size_t)E_NUM * T_TOK * H_DIM];  // 32 MB gathered fp16 hs
__device__ __half g_act[(size_t)E_NUM * T_TOK * I_DIM];  // 64 MB fp16
__device__ float  g_y[(size_t)E_NUM * T_TOK * H_DIM];    // 64 MB

// ---------------- helpers ----------------
__device__ __forceinline__ uint32_t f2h2(float lo, float hi) {
    __half2 h;
    h.x = __float2half_rn(lo);
    h.y = __float2half_rn(hi);
    return *reinterpret_cast<uint32_t*>(&h);
}
__device__ __forceinline__ void mma_f16(float* c, const uint32_t* a, const uint32_t* b) {
    asm volatile(
        "mma.sync.aligned.m16n8k16.row.col.f32.f16.f16.f32 "
        "{%0,%1,%2,%3}, {%4,%5,%6,%7}, {%8,%9}, {%0,%1,%2,%3};"
        : "+f"(c[0]), "+f"(c[1]), "+f"(c[2]), "+f"(c[3])
        : "r"(a[0]), "r"(a[1]), "r"(a[2]), "r"(a[3]), "r"(b[0]), "r"(b[1]));
}

// ---------------- small kernels ----------------
__global__ void zero_counts_kernel() {
    if (threadIdx.x < E_NUM) g_count[threadIdx.x] = 0;
}

__global__ void router_kernel(const float* __restrict__ hs, const float* __restrict__ gw) {
    int t = blockIdx.x;
    const float* x = hs + (size_t)t * H_DIM;
    float acc[E_NUM];
#pragma unroll
    for (int e = 0; e < E_NUM; e++) acc[e] = 0.f;
    for (int j = threadIdx.x; j < H_DIM; j += blockDim.x) {
        float xv = x[j];
        const float4* grow = reinterpret_cast<const float4*>(gw + (size_t)j * E_NUM);
        float4 g0 = grow[0], g1 = grow[1];
        acc[0] += xv * g0.x; acc[1] += xv * g0.y; acc[2] += xv * g0.z; acc[3] += xv * g0.w;
        acc[4] += xv * g1.x; acc[5] += xv * g1.y; acc[6] += xv * g1.z; acc[7] += xv * g1.w;
    }
#pragma unroll
    for (int off = 16; off > 0; off >>= 1)
#pragma unroll
        for (int e = 0; e < E_NUM; e++)
            acc[e] += __shfl_xor_sync(0xffffffffu, acc[e], off);
    __shared__ float s[4][E_NUM];
    int warp = threadIdx.x >> 5, lane = threadIdx.x & 31;
    if (lane == 0)
#pragma unroll
        for (int e = 0; e < E_NUM; e++) s[warp][e] = acc[e];
    __syncthreads();
    if (threadIdx.x == 0) {
        float l[E_NUM];
#pragma unroll
        for (int e = 0; e < E_NUM; e++)
            l[e] = tanhf((s[0][e] + s[1][e] + s[2][e] + s[3][e]) * (1.0f / 30.0f));
        int i0 = 0;
#pragma unroll
        for (int e = 1; e < E_NUM; e++) if (l[e] > l[i0]) i0 = e;
        int i1 = (i0 == 0) ? 1 : 0;
#pragma unroll
        for (int e = 0; e < E_NUM; e++) if (e != i0 && l[e] > l[i1]) i1 = e;
        float d  = l[i1] - l[i0];
        float ed = expf(d);
        float inv = 1.0f / (1.0f + ed);
        float p0 = inv, p1 = ed * inv;
        int p = atomicAdd(&g_count[i0], 1);
        g_tok[i0][p] = t; g_wt[i0][p] = p0; g_slot[t][0] = i0 * T_TOK + p;
        p = atomicAdd(&g_count[i1], 1);
        g_tok[i1][p] = t; g_wt[i1][p] = p1; g_slot[t][1] = i1 * T_TOK + p;
    }
}

// gather hs rows into fp16 slot-order buffer (per expert)
__global__ __launch_bounds__(256) void gather_x_kernel(const float* __restrict__ hs) {
    int e = blockIdx.x;
    int count = g_count[e];
    int s = blockIdx.y * 8 + (threadIdx.x >> 5);
    if (s >= count) return;
    int lane = threadIdx.x & 31;
    int tok = g_tok[e][s];
    const float4* src = reinterpret_cast<const float4*>(hs + (size_t)tok * H_DIM);
    uint2* dst = reinterpret_cast<uint2*>(g_x16 + ((size_t)e * T_TOK + s) * H_DIM);
#pragma unroll
    for (int i = 0; i < 8; ++i) {
        float4 v = src[lane + i * 32];
        dst[lane + i * 32] = make_uint2(f2h2(v.x, v.y), f2h2(v.z, v.w));
    }
}

__device__ __forceinline__ float gelu_tanh(float g) {
    float c = 0.7978845608028654f * (g + 0.044715f * g * g * g);
    return 0.5f * g * (1.0f + tanhf(c));
}

// ===== fragment math: fp16 m16n8k16, warp tile 64x32, 16 warps (2m x 8n) =====
#define GX_MMA(s)                                                                     \
    {                                                                                 \
        const uint32_t* As = sm32 + (s) * 6144;                                       \
        const uint32_t* Bs = As + 2048;                                               \
        const int kl = lane & 3, dn = lane >> 2;                                      \
        _Pragma("unroll")                                                             \
        for (int ks = 0; ks < 2; ++ks) {                                              \
            uint4 af[4];                                                              \
            _Pragma("unroll")                                                         \
            for (int mt = 0; mt < 4; ++mt)                                            \
                af[mt] = *reinterpret_cast<const uint4*>(                             \
                    As + ((ks * 8 + wm * 4 + mt) * 32 + lane) * 4);                   \
            uint2 bf[4];                                                              \
            _Pragma("unroll")                                                         \
            for (int nt = 0; nt < 4; ++nt) {                                          \
                int pn = (wn * 32 + nt * 8 + dn) ^ (kl << 3);                         \
                bf[nt].x = Bs[(ks * 8 + kl) * 256 + pn];                              \
                bf[nt].y = Bs[(ks * 8 + kl + 4) * 256 + pn];                          \
            }                                                                         \
            _Pragma("unroll")                                                         \
            for (int mt = 0; mt < 4; ++mt)                                            \
                _Pragma("unroll")                                                     \
                for (int nt = 0; nt < 4; ++nt)                                        \
                    mma_f16(acc[mt][nt], (const uint32_t*)&af[mt], (const uint32_t*)&bf[nt]); \
        }                                                                             \
    }

// A store mapping for a 4-k group at (m, kq)
#define A_STORE_WORDS(As, m, kq, w0, w1)                                              \
    {                                                                                 \
        int kin = (kq) & 15, ks = (kq) >> 4;                                          \
        int c = (kin >> 1) & 3;                                                       \
        int reg = ((kin & 8) >> 2) + (((m) & 8) >> 3);                                \
        int lane0 = (((m) & 7) << 2) + c;                                             \
        int base = ((ks * 8 + ((m) >> 4)) * 32);                                      \
        (As)[(base + lane0) * 4 + reg] = (w0);                                        \
        (As)[(base + lane0 + 1) * 4 + reg] = (w1);                                    \
    }

// ============================================================================
// GEMM1: act_fp16 = gelu(X@wg)*(X@wu); A from g_x16.
// CTA M=128 x Nphys=256, 512 thr, kb=32, 3-stage, 1 sync/chunk.
// Grid: x = mblk (fastest), y = e, z = nblk (slowest) -> L2 weight reuse.
// ============================================================================
__global__ __launch_bounds__(512, 1)
void gemm1_kernel(const float* __restrict__ wg,
                  const float* __restrict__ wu) {
    const int e = blockIdx.y;
    const int count = g_count[e];
    const int m0 = blockIdx.x * 128;
    if (m0 >= count) return;
    const int n0 = blockIdx.z * 128;          // logical I-column base

    extern __shared__ uint32_t sm32[];

    const int tid = threadIdx.x, wid = tid >> 5, lane = tid & 31;
    const int wm = wid & 1, wn = wid >> 1;

    const __half* xp  = g_x16 + (size_t)e * T_TOK * H_DIM;
    const float*  wgp = wg + (size_t)e * H_DIM * I_DIM + n0;
    const float*  wup = wu + (size_t)e * H_DIM * I_DIM + n0;

    float acc[4][4][4];
#pragma unroll
    for (int i = 0; i < 4; i++)
#pragma unroll
        for (int j = 0; j < 4; j++)
#pragma unroll
            for (int q = 0; q < 4; q++) acc[i][j][q] = 0.f;

    uint2 rAw[2];
    uint4 rBw[2];

#define G1_LOAD(k0)                                                                   \
    {                                                                                 \
        _Pragma("unroll")                                                             \
        for (int it = 0; it < 2; ++it) {                                              \
            int f = tid + it * 512;                                                   \
            int m = f >> 3, kq = (f & 7) << 2;                                        \
            int gp = m0 + m;                                                          \
            rAw[it] = (gp < count)                                                    \
                ? *reinterpret_cast<const uint2*>(xp + (size_t)gp * H_DIM + (k0) + kq) \
                : make_uint2(0u, 0u);                                                 \
        }                                                                             \
        _Pragma("unroll")                                                             \
        for (int it = 0; it < 2; ++it) {                                              \
            int f = tid + it * 512;                                                   \
            int n4 = f & 63, k2 = f >> 6;                                             \
            int blk = n4 >> 1;                                                        \
            const float* bsrc = (blk & 1) ? wup : wgp;                                \
            int srcoff = (blk >> 1) * 8 + (n4 & 1) * 4;                               \
            float4 r0 = *reinterpret_cast<const float4*>(                             \
                bsrc + (size_t)((k0) + 2 * k2) * I_DIM + srcoff);                     \
            float4 r1 = *reinterpret_cast<const float4*>(                             \
                bsrc + (size_t)((k0) + 2 * k2 + 1) * I_DIM + srcoff);                 \
            rBw[it].x = f2h2(r0.x, r1.x);                                             \
            rBw[it].y = f2h2(r0.y, r1.y);                                             \
            rBw[it].z = f2h2(r0.z, r1.z);                                             \
            rBw[it].w = f2h2(r0.w, r1.w);                                             \
        }                                                                             \
    }

#define G1_STORE(s)                                                                   \
    {                                                                                 \
        uint32_t* As = sm32 + (s) * 6144;                                             \
        uint32_t* Bs = As + 2048;                                                     \
        _Pragma("unroll")                                                             \
        for (int it = 0; it < 2; ++it) {                                              \
            int f = tid + it * 512;                                                   \
            int m = f >> 3, kq = (f & 7) << 2;                                        \
            A_STORE_WORDS(As, m, kq, rAw[it].x, rAw[it].y);                           \
        }                                                                             \
        _Pragma("unroll")                                                             \
        for (int it = 0; it < 2; ++it) {                                              \
            int f = tid + it * 512;                                                   \
            int n4 = f & 63, k2 = f >> 6;                                             \
            int pn4 = n4 ^ ((k2 & 3) << 1);                                           \
            *reinterpret_cast<uint4*>(Bs + k2 * 256 + pn4 * 4) = rBw[it];             \
        }                                                                             \
    }

    const int NC = H_DIM / 32;   // 32
    G1_LOAD(0);
    G1_STORE(0);
    G1_LOAD(32);
    __syncthreads();
    {
        int cs = 0;
        for (int c = 0; c < NC; ++c) {
            int st = (cs == 2) ? 0 : cs + 1;
            if (c + 1 < NC) G1_STORE(st);
            if (c + 2 < NC) G1_LOAD((c + 2) * 32);
            GX_MMA(cs);
            __syncthreads();
            cs = st;
        }
    }

    // ---- epilogue: (acc[mt][2j], acc[mt][2j+1]) = (g,u); write fp16 ----
#pragma unroll
    for (int mt = 0; mt < 4; ++mt) {
        int row_base = wm * 64 + mt * 16 + (lane >> 2);
#pragma unroll
        for (int h = 0; h < 2; ++h) {
            int gpos = m0 + row_base + h * 8;
            if (gpos >= count) continue;
            __half* dst = g_act + ((size_t)e * T_TOK + gpos) * I_DIM + n0;
#pragma unroll
            for (int j = 0; j < 2; ++j) {
                int col = (2 * wn + j) * 8 + (lane & 3) * 2;
                uint32_t w = f2h2(
                    gelu_tanh(acc[mt][2 * j][2 * h])     * acc[mt][2 * j + 1][2 * h],
                    gelu_tanh(acc[mt][2 * j][2 * h + 1]) * acc[mt][2 * j + 1][2 * h + 1]);
                *reinterpret_cast<uint32_t*>(dst + col) = w;
            }
        }
    }
#undef G1_LOAD
#undef G1_STORE
}

// ============================================================================
// GEMM2 (monolithic, R11-validated): y = weight * (act_fp16 @ wd).
// CTA 128x256, 512 thr, kb=32, 3-stage.
// Grid: x = mblk (fastest), y = e, z = nblk (slowest).
// ============================================================================
__global__ __launch_bounds__(512, 1)
void gemm2_kernel(const float* __restrict__ wd) {
    const int e = blockIdx.y;
    const int count = g_count[e];
    const int m0 = blockIdx.x * 128;
    if (m0 >= count) return;
    const int n0 = blockIdx.z * 256;

    extern __shared__ uint32_t sm32[];

    const int tid = threadIdx.x, wid = tid >> 5, lane = tid & 31;
    const int wm = wid & 1, wn = wid >> 1;

    const __half* actp = g_act + (size_t)e * T_TOK * I_DIM;
    const float*  wdp  = wd + (size_t)e * I_DIM * H_DIM + n0;

    float acc[4][4][4];
#pragma unroll
    for (int i = 0; i < 4; i++)
#pragma unroll
        for (int j = 0; j < 4; j++)
#pragma unroll
            for (int q = 0; q < 4; q++) acc[i][j][q] = 0.f;

    uint2 rAw[2];
    uint4 rBw[2];

#define G2_LOAD(k0)                                                                   \
    {                                                                                 \
        _Pragma("unroll")                                                             \
        for (int it = 0; it < 2; ++it) {                                              \
            int f = tid + it * 512;                                                   \
            int m = f >> 3, kq = (f & 7) << 2;                                        \
            int gp = m0 + m;                                                          \
            rAw[it] = (gp < count)                                                    \
                ? *reinterpret_cast<const uint2*>(actp + (size_t)gp * I_DIM + (k0) + kq) \
                : make_uint2(0u, 0u);                                                 \
        }                                                                             \
        _Pragma("unroll")                                                             \
        for (int it = 0; it < 2; ++it) {                                              \
            int f = tid + it * 512;                                                   \
            int n4 = f & 63, k2 = f >> 6;                                             \
            float4 r0 = *reinterpret_cast<const float4*>(                             \
                wdp + (size_t)((k0) + 2 * k2) * H_DIM + n4 * 4);                      \
            float4 r1 = *reinterpret_cast<const float4*>(                             \
                wdp + (size_t)((k0) + 2 * k2 + 1) * H_DIM + n4 * 4);                  \
            rBw[it].x = f2h2(r0.x, r1.x);                                             \
            rBw[it].y = f2h2(r0.y, r1.y);                                             \
            rBw[it].z = f2h2(r0.z, r1.z);                                             \
            rBw[it].w = f2h2(r0.w, r1.w);                                             \
        }                                                                             \
    }

#define G2_STORE(s)                                                                   \
    {                                                                                 \
        uint32_t* As = sm32 + (s) * 6144;                                             \
        uint32_t* Bs = As + 2048;                                                     \
        _Pragma("unroll")                                                             \
        for (int it = 0; it < 2; ++it) {                                              \
            int f = tid + it * 512;                                                   \
            int m = f >> 3, kq = (f & 7) << 2;                                        \
            A_STORE_WORDS(As, m, kq, rAw[it].x, rAw[it].y);                           \
        }                                                                             \
        _Pragma("unroll")                                                             \
        for (int it = 0; it < 2; ++it) {                                              \
            int f = tid + it * 512;                                                   \
            int n4 = f & 63, k2 = f >> 6;                                             \
            int pn4 = n4 ^ ((k2 & 3) << 1);                                           \
            *reinterpret_cast<uint4*>(Bs + k2 * 256 + pn4 * 4) = rBw[it];             \
        }                                                                             \
    }

    const int NC = I_DIM / 32;   // 64
    G2_LOAD(0);
    G2_STORE(0);
    G2_LOAD(32);
    __syncthreads();
    {
        int cs = 0;
        for (int c = 0; c < NC; ++c) {
            int st = (cs == 2) ? 0 : cs + 1;
            if (c + 1 < NC) G2_STORE(st);
            if (c + 2 < NC) G2_LOAD((c + 2) * 32);
            GX_MMA(cs);
            __syncthreads();
            cs = st;
        }
    }

    // ---- epilogue: scale by combine weight, write slot buffer ----
#pragma unroll
    for (int mt = 0; mt < 4; ++mt) {
        int row_base = wm * 64 + mt * 16 + (lane >> 2);
#pragma unroll
        for (int h = 0; h < 2; ++h) {
            int gpos = m0 + row_base + h * 8;
            if (gpos >= count) continue;
            float w = g_wt[e][gpos];
            float* dst = g_y + ((size_t)e * T_TOK + gpos) * H_DIM + n0;
#pragma unroll
            for (int nt = 0; nt < 4; ++nt) {
                int col = wn * 32 + nt * 8 + (lane & 3) * 2;
                float2 o;
                o.x = w * acc[mt][nt][2 * h];
                o.y = w * acc[mt][nt][2 * h + 1];
                *reinterpret_cast<float2*>(dst + col) = o;
            }
        }
    }
#undef G2_LOAD
#undef G2_STORE
#undef GX_MMA
}

// ---------------- combine: out[t] = y[slot0] + y[slot1] ----------------
__global__ __launch_bounds__(256) void combine_kernel(float* __restrict__ out) {
    int t = blockIdx.x;
    int s0 = g_slot[t][0], s1 = g_slot[t][1];
    const float4* y0 = reinterpret_cast<const float4*>(g_y + (size_t)s0 * H_DIM);
    const float4* y1 = reinterpret_cast<const float4*>(g_y + (size_t)s1 * H_DIM);
    float4* o = reinterpret_cast<float4*>(out + (size_t)t * H_DIM);
    int c = threadIdx.x;
    float4 a = y0[c], b = y1[c];
    o[c] = make_float4(a.x + b.x, a.y + b.y, a.z + b.z, a.w + b.w);
}

// ---------------- launch ----------------
extern "C" void kernel_launch(void* const* d_in, const int* in_sizes, int n_in,
                              void* d_out, int out_size) {
    const float* hs = (const float*)d_in[0];   // [T, H]
    const float* gw = (const float*)d_in[1];   // [H, E]
    const float* wg = (const float*)d_in[2];   // [E, H, I]
    const float* wu = (const float*)d_in[3];   // [E, H, I]
    const float* wd = (const float*)d_in[4];   // [E, I, H]
    float* out = (float*)d_out;                // [T, H]

    static bool attr_done = false;
    if (!attr_done) {
        cudaFuncSetAttribute(gemm1_kernel, cudaFuncAttributeMaxDynamicSharedMemorySize, 73728);
        cudaFuncSetAttribute(gemm2_kernel, cudaFuncAttributeMaxDynamicSharedMemorySize, 73728);
        attr_done = true;
    }

    zero_counts_kernel<<<1, 32>>>();
    router_kernel<<<T_TOK, 128>>>(hs, gw);
    gather_x_kernel<<<dim3(E_NUM, T_TOK / 8), 256>>>(hs);

    // mblk fastest, nblk slowest -> concurrent CTAs share weight slabs in L2
    dim3 g1(T_TOK / 128, E_NUM, I_DIM / 128);   // (16, 8, 16)
    gemm1_kernel<<<g1, 512, 73728>>>(wg, wu);

    dim3 g2(T_TOK / 128, E_NUM, H_DIM / 256);   // (16, 8, 4)
    gemm2_kernel<<<g2, 512, 73728>>>(wd);

    combine_kernel<<<T_TOK, 256>>>(out);
}

// round 14
// speedup vs baseline: 1.3979x; 1.2016x over previous
#include <cuda_runtime.h>
#include <cuda_fp16.h>
#include <math.h>
#include <stdint.h>

#define T_TOK 2048
#define H_DIM 1024
#define E_NUM 8
#define I_DIM 2048

// ---------------- device scratch ----------------
__device__ int      g_count[E_NUM];
__device__ int      g_tok[E_NUM][T_TOK];
__device__ float    g_wt[E_NUM][T_TOK];
__device__ int      g_slot[T_TOK][2];
// Pre-packed operand images (exact smem layouts, fp16 words):
__device__ uint32_t g_x16A[(size_t)E_NUM * 16 * 32 * 2048];  // 32 MB: gemm1 A tiles
__device__ uint32_t g_w1[(size_t)E_NUM * 16 * 32 * 4096];    // 64 MB: gemm1 B tiles (wg/wu interleaved)
__device__ uint32_t g_w2[(size_t)E_NUM * 4 * 64 * 4096];     // 32 MB: gemm2 B tiles (wd)
__device__ __half   g_act[(size_t)E_NUM * T_TOK * I_DIM];    // 64 MB fp16
__device__ float    g_y[(size_t)E_NUM * T_TOK * H_DIM];      // 64 MB

// ---------------- helpers ----------------
__device__ __forceinline__ uint32_t f2h2(float lo, float hi) {
    __half2 h;
    h.x = __float2half_rn(lo);
    h.y = __float2half_rn(hi);
    return *reinterpret_cast<uint32_t*>(&h);
}
__device__ __forceinline__ void mma_f16(float* c, const uint32_t* a, const uint32_t* b) {
    asm volatile(
        "mma.sync.aligned.m16n8k16.row.col.f32.f16.f16.f32 "
        "{%0,%1,%2,%3}, {%4,%5,%6,%7}, {%8,%9}, {%0,%1,%2,%3};"
        : "+f"(c[0]), "+f"(c[1]), "+f"(c[2]), "+f"(c[3])
        : "r"(a[0]), "r"(a[1]), "r"(a[2]), "r"(a[3]), "r"(b[0]), "r"(b[1]));
}
#define CP_ASYNC16(smem_u32, gptr) \
    asm volatile("cp.async.cg.shared.global [%0], [%1], 16;" :: "r"(smem_u32), "l"(gptr) : "memory")
#define CP_COMMIT() asm volatile("cp.async.commit_group;" ::: "memory")
#define CP_WAIT2()  asm volatile("cp.async.wait_group 2;" ::: "memory")

// A-fragment word index for (m in [0,128), k2 in [0,16)) — algebra identical to
// the validated A_STORE_WORDS mapping.
__device__ __forceinline__ int a_word_idx(int m, int k2) {
    int ks = k2 >> 3;
    int reg = ((k2 & 4) >> 1) + ((m & 8) >> 3);
    int lane0 = ((m & 7) << 2) + (k2 & 3);
    return (((ks * 8 + (m >> 4)) * 32) + lane0) * 4 + reg;
}
// A store mapping for a 4-k group at (m, kq) — validated R11
#define A_STORE_WORDS(As, m, kq, w0, w1)                                              \
    {                                                                                 \
        int kin = (kq) & 15, ks = (kq) >> 4;                                          \
        int c_ = (kin >> 1) & 3;                                                      \
        int reg = ((kin & 8) >> 2) + (((m) & 8) >> 3);                                \
        int lane0 = (((m) & 7) << 2) + c_;                                            \
        int base = ((ks * 8 + ((m) >> 4)) * 32);                                      \
        (As)[(base + lane0) * 4 + reg] = (w0);                                        \
        (As)[(base + lane0 + 1) * 4 + reg] = (w1);                                    \
    }

// ---------------- small kernels ----------------
__global__ void zero_counts_kernel() {
    if (threadIdx.x < E_NUM) g_count[threadIdx.x] = 0;
}

__global__ void router_kernel(const float* __restrict__ hs, const float* __restrict__ gw) {
    int t = blockIdx.x;
    const float* x = hs + (size_t)t * H_DIM;
    float acc[E_NUM];
#pragma unroll
    for (int e = 0; e < E_NUM; e++) acc[e] = 0.f;
    for (int j = threadIdx.x; j < H_DIM; j += blockDim.x) {
        float xv = x[j];
        const float4* grow = reinterpret_cast<const float4*>(gw + (size_t)j * E_NUM);
        float4 g0 = grow[0], g1 = grow[1];
        acc[0] += xv * g0.x; acc[1] += xv * g0.y; acc[2] += xv * g0.z; acc[3] += xv * g0.w;
        acc[4] += xv * g1.x; acc[5] += xv * g1.y; acc[6] += xv * g1.z; acc[7] += xv * g1.w;
    }
#pragma unroll
    for (int off = 16; off > 0; off >>= 1)
#pragma unroll
        for (int e = 0; e < E_NUM; e++)
            acc[e] += __shfl_xor_sync(0xffffffffu, acc[e], off);
    __shared__ float s[4][E_NUM];
    int warp = threadIdx.x >> 5, lane = threadIdx.x & 31;
    if (lane == 0)
#pragma unroll
        for (int e = 0; e < E_NUM; e++) s[warp][e] = acc[e];
    __syncthreads();
    if (threadIdx.x == 0) {
        float l[E_NUM];
#pragma unroll
        for (int e = 0; e < E_NUM; e++)
            l[e] = tanhf((s[0][e] + s[1][e] + s[2][e] + s[3][e]) * (1.0f / 30.0f));
        int i0 = 0;
#pragma unroll
        for (int e = 1; e < E_NUM; e++) if (l[e] > l[i0]) i0 = e;
        int i1 = (i0 == 0) ? 1 : 0;
#pragma unroll
        for (int e = 0; e < E_NUM; e++) if (e != i0 && l[e] > l[i1]) i1 = e;
        float d  = l[i1] - l[i0];
        float ed = expf(d);
        float inv = 1.0f / (1.0f + ed);
        float p0 = inv, p1 = ed * inv;
        int p = atomicAdd(&g_count[i0], 1);
        g_tok[i0][p] = t; g_wt[i0][p] = p0; g_slot[t][0] = i0 * T_TOK + p;
        p = atomicAdd(&g_count[i1], 1);
        g_tok[i1][p] = t; g_wt[i1][p] = p1; g_slot[t][1] = i1 * T_TOK + p;
    }
}

// gather hs rows into fp16 A-fragment tile images (zero-fill pad slots)
__global__ __launch_bounds__(256) void gather_x_kernel(const float* __restrict__ hs) {
    int e = blockIdx.x;
    int count = g_count[e];
    int s = blockIdx.y * 8 + (threadIdx.x >> 5);
    int lane = threadIdx.x & 31;
    int mblk = s >> 7, ml = s & 127;
    uint32_t* base = g_x16A + ((size_t)(e * 16 + mblk)) * 32 * 2048;
    if (s < count) {
        int tok = g_tok[e][s];
        const float2* src = reinterpret_cast<const float2*>(hs + (size_t)tok * H_DIM);
#pragma unroll
        for (int i = 0; i < 16; ++i) {
            int w = lane + i * 32;                 // global k2 index, 0..511
            float2 v = src[w];
            base[(size_t)(w >> 4) * 2048 + a_word_idx(ml, w & 15)] = f2h2(v.x, v.y);
        }
    } else {
#pragma unroll
        for (int i = 0; i < 16; ++i) {
            int w = lane + i * 32;
            base[(size_t)(w >> 4) * 2048 + a_word_idx(ml, w & 15)] = 0u;
        }
    }
}

// pack wg/wu into gemm1 B tiles — body replicates the validated staged-B code
__global__ __launch_bounds__(512) void pack_w1_kernel(const float* __restrict__ wg,
                                                      const float* __restrict__ wu) {
    const int chunk = blockIdx.x, nblk = blockIdx.y, e = blockIdx.z;
    const float* wgp = wg + (size_t)e * H_DIM * I_DIM + nblk * 128;
    const float* wup = wu + (size_t)e * H_DIM * I_DIM + nblk * 128;
    uint32_t* tile = g_w1 + (((size_t)(e * 16 + nblk)) * 32 + chunk) * 4096;
    const int k0 = chunk * 32, tid = threadIdx.x;
#pragma unroll
    for (int it = 0; it < 2; ++it) {
        int f = tid + it * 512;
        int n4 = f & 63, k2 = f >> 6;
        int blk = n4 >> 1;
        const float* bsrc = (blk & 1) ? wup : wgp;
        int srcoff = (blk >> 1) * 8 + (n4 & 1) * 4;
        float4 r0 = *reinterpret_cast<const float4*>(bsrc + (size_t)(k0 + 2 * k2) * I_DIM + srcoff);
        float4 r1 = *reinterpret_cast<const float4*>(bsrc + (size_t)(k0 + 2 * k2 + 1) * I_DIM + srcoff);
        int pn4 = n4 ^ ((k2 & 3) << 1);
        *reinterpret_cast<uint4*>(tile + k2 * 256 + pn4 * 4) =
            make_uint4(f2h2(r0.x, r1.x), f2h2(r0.y, r1.y), f2h2(r0.z, r1.z), f2h2(r0.w, r1.w));
    }
}

// pack wd into gemm2 B tiles
__global__ __launch_bounds__(512) void pack_w2_kernel(const float* __restrict__ wd) {
    const int chunk = blockIdx.x, nblk = blockIdx.y, e = blockIdx.z;
    const float* wdp = wd + (size_t)e * I_DIM * H_DIM + nblk * 256;
    uint32_t* tile = g_w2 + (((size_t)(e * 4 + nblk)) * 64 + chunk) * 4096;
    const int k0 = chunk * 32, tid = threadIdx.x;
#pragma unroll
    for (int it = 0; it < 2; ++it) {
        int f = tid + it * 512;
        int n4 = f & 63, k2 = f >> 6;
        float4 r0 = *reinterpret_cast<const float4*>(wdp + (size_t)(k0 + 2 * k2) * H_DIM + n4 * 4);
        float4 r1 = *reinterpret_cast<const float4*>(wdp + (size_t)(k0 + 2 * k2 + 1) * H_DIM + n4 * 4);
        int pn4 = n4 ^ ((k2 & 3) << 1);
        *reinterpret_cast<uint4*>(tile + k2 * 256 + pn4 * 4) =
            make_uint4(f2h2(r0.x, r1.x), f2h2(r0.y, r1.y), f2h2(r0.z, r1.z), f2h2(r0.w, r1.w));
    }
}

__device__ __forceinline__ float gelu_tanh(float g) {
    float c = 0.7978845608028654f * (g + 0.044715f * g * g * g);
    return 0.5f * g * (1.0f + tanhf(c));
}

// ===== fragment math: fp16 m16n8k16, warp tile 64x32, 16 warps (2m x 8n) =====
#define GX_MMA(s)                                                                     \
    {                                                                                 \
        const uint32_t* As = sm32 + (s) * 6144;                                       \
        const uint32_t* Bs = As + 2048;                                               \
        const int kl = lane & 3, dn = lane >> 2;                                      \
        _Pragma("unroll")                                                             \
        for (int ks = 0; ks < 2; ++ks) {                                              \
            uint4 af[4];                                                              \
            _Pragma("unroll")                                                         \
            for (int mt = 0; mt < 4; ++mt)                                            \
                af[mt] = *reinterpret_cast<const uint4*>(                             \
                    As + ((ks * 8 + wm * 4 + mt) * 32 + lane) * 4);                   \
            uint2 bf[4];                                                              \
            _Pragma("unroll")                                                         \
            for (int nt = 0; nt < 4; ++nt) {                                          \
                int pn = (wn * 32 + nt * 8 + dn) ^ (kl << 3);                         \
                bf[nt].x = Bs[(ks * 8 + kl) * 256 + pn];                              \
                bf[nt].y = Bs[(ks * 8 + kl + 4) * 256 + pn];                          \
            }                                                                         \
            _Pragma("unroll")                                                         \
            for (int mt = 0; mt < 4; ++mt)                                            \
                _Pragma("unroll")                                                     \
                for (int nt = 0; nt < 4; ++nt)                                        \
                    mma_f16(acc[mt][nt], (const uint32_t*)&af[mt], (const uint32_t*)&bf[nt]); \
        }                                                                             \
    }

// ============================================================================
// GEMM1: act_fp16 = gelu(X@wg)*(X@wu). Fully cp.async staging from packed tiles.
// CTA M=128 x Nphys=256, 512 thr, kb=32, 3-stage.
// Grid: x = mblk (fastest), y = e, z = nblk (slowest).
// ============================================================================
__global__ __launch_bounds__(512, 1)
void gemm1_kernel() {
    const int e = blockIdx.y;
    const int count = g_count[e];
    const int m0 = blockIdx.x * 128;
    if (m0 >= count) return;
    const int n0 = blockIdx.z * 128;

    extern __shared__ uint32_t sm32[];
    const uint32_t sbase = (uint32_t)__cvta_generic_to_shared(sm32);

    const int tid = threadIdx.x, wid = tid >> 5, lane = tid & 31;
    const int wm = wid & 1, wn = wid >> 1;

    const uint4* At = reinterpret_cast<const uint4*>(
        g_x16A + ((size_t)(e * 16 + blockIdx.x)) * 32 * 2048);
    const uint4* Bt = reinterpret_cast<const uint4*>(
        g_w1 + ((size_t)(e * 16 + blockIdx.z)) * 32 * 4096);

    float acc[4][4][4];
#pragma unroll
    for (int i = 0; i < 4; i++)
#pragma unroll
        for (int j = 0; j < 4; j++)
#pragma unroll
            for (int q = 0; q < 4; q++) acc[i][j][q] = 0.f;

#define G1_ISSUE(s, c)                                                                \
    {                                                                                 \
        CP_ASYNC16(sbase + ((s) * 6144 + tid * 4) * 4, At + (size_t)(c) * 512 + tid); \
        CP_ASYNC16(sbase + ((s) * 6144 + 2048 + tid * 4) * 4,                         \
                   Bt + (size_t)(c) * 1024 + tid);                                    \
        CP_ASYNC16(sbase + ((s) * 6144 + 4096 + tid * 4) * 4,                         \
                   Bt + (size_t)(c) * 1024 + 512 + tid);                              \
    }

    const int NC = 32;
    G1_ISSUE(0, 0); CP_COMMIT();
    G1_ISSUE(1, 1); CP_COMMIT();
    for (int c = 0; c < NC; ++c) {
        if (c + 2 < NC) G1_ISSUE((c + 2) % 3, c + 2);
        CP_COMMIT();
        CP_WAIT2();
        __syncthreads();
        GX_MMA(c % 3);
        __syncthreads();
    }
#undef G1_ISSUE

    // ---- epilogue: (acc[mt][2j], acc[mt][2j+1]) = (g,u); write fp16 ----
#pragma unroll
    for (int mt = 0; mt < 4; ++mt) {
        int row_base = wm * 64 + mt * 16 + (lane >> 2);
#pragma unroll
        for (int h = 0; h < 2; ++h) {
            int gpos = m0 + row_base + h * 8;
            if (gpos >= count) continue;
            __half* dst = g_act + ((size_t)e * T_TOK + gpos) * I_DIM + n0;
#pragma unroll
            for (int j = 0; j < 2; ++j) {
                int col = (2 * wn + j) * 8 + (lane & 3) * 2;
                uint32_t w = f2h2(
                    gelu_tanh(acc[mt][2 * j][2 * h])     * acc[mt][2 * j + 1][2 * h],
                    gelu_tanh(acc[mt][2 * j][2 * h + 1]) * acc[mt][2 * j + 1][2 * h + 1]);
                *reinterpret_cast<uint32_t*>(dst + col) = w;
            }
        }
    }
}

// ============================================================================
// GEMM2: y = weight * (act_fp16 @ wd). A register-staged (unchanged), B cp.async.
// CTA 128x256, 512 thr, kb=32, 3-stage. Grid: x=mblk, y=e, z=nblk.
// ============================================================================
__global__ __launch_bounds__(512, 1)
void gemm2_kernel() {
    const int e = blockIdx.y;
    const int count = g_count[e];
    const int m0 = blockIdx.x * 128;
    if (m0 >= count) return;
    const int n0 = blockIdx.z * 256;

    extern __shared__ uint32_t sm32[];
    const uint32_t sbase = (uint32_t)__cvta_generic_to_shared(sm32);

    const int tid = threadIdx.x, wid = tid >> 5, lane = tid & 31;
    const int wm = wid & 1, wn = wid >> 1;

    const __half* actp = g_act + (size_t)e * T_TOK * I_DIM;
    const uint4* Bt = reinterpret_cast<const uint4*>(
        g_w2 + ((size_t)(e * 4 + blockIdx.z)) * 64 * 4096);

    float acc[4][4][4];
#pragma unroll
    for (int i = 0; i < 4; i++)
#pragma unroll
        for (int j = 0; j < 4; j++)
#pragma unroll
            for (int q = 0; q < 4; q++) acc[i][j][q] = 0.f;

#define G2_A_STAGE(s, c)                                                              \
    {                                                                                 \
        uint32_t* As = sm32 + (s) * 6144;                                             \
        const int k0 = (c) * 32;                                                      \
        _Pragma("unroll")                                                             \
        for (int it = 0; it < 2; ++it) {                                              \
            int f = tid + it * 512;                                                   \
            int m = f >> 3, kq = (f & 7) << 2;                                        \
            int gp = m0 + m;                                                          \
            uint2 aw = (gp < count)                                                   \
                ? *reinterpret_cast<const uint2*>(actp + (size_t)gp * I_DIM + k0 + kq) \
                : make_uint2(0u, 0u);                                                 \
            A_STORE_WORDS(As, m, kq, aw.x, aw.y);                                     \
        }                                                                             \
    }
#define G2_B_ISSUE(s, c)                                                              \
    {                                                                                 \
        CP_ASYNC16(sbase + ((s) * 6144 + 2048 + tid * 4) * 4,                         \
                   Bt + (size_t)(c) * 1024 + tid);                                    \
        CP_ASYNC16(sbase + ((s) * 6144 + 4096 + tid * 4) * 4,                         \
                   Bt + (size_t)(c) * 1024 + 512 + tid);                              \
    }

    const int NC = 64;
    G2_A_STAGE(0, 0); G2_B_ISSUE(0, 0); CP_COMMIT();
    G2_A_STAGE(1, 1); G2_B_ISSUE(1, 1); CP_COMMIT();
    for (int c = 0; c < NC; ++c) {
        if (c + 2 < NC) {
            G2_A_STAGE((c + 2) % 3, c + 2);
            G2_B_ISSUE((c + 2) % 3, c + 2);
        }
        CP_COMMIT();
        CP_WAIT2();
        __syncthreads();
        GX_MMA(c % 3);
        __syncthreads();
    }
#undef G2_A_STAGE
#undef G2_B_ISSUE

    // ---- epilogue: scale by combine weight, write slot buffer ----
#pragma unroll
    for (int mt = 0; mt < 4; ++mt) {
        int row_base = wm * 64 + mt * 16 + (lane >> 2);
#pragma unroll
        for (int h = 0; h < 2; ++h) {
            int gpos = m0 + row_base + h * 8;
            if (gpos >= count) continue;
            float w = g_wt[e][gpos];
            float* dst = g_y + ((size_t)e * T_TOK + gpos) * H_DIM + n0;
#pragma unroll
            for (int nt = 0; nt < 4; ++nt) {
                int col = wn * 32 + nt * 8 + (lane & 3) * 2;
                float2 o;
                o.x = w * acc[mt][nt][2 * h];
                o.y = w * acc[mt][nt][2 * h + 1];
                *reinterpret_cast<float2*>(dst + col) = o;
            }
        }
    }
}

// ---------------- combine: out[t] = y[slot0] + y[slot1] ----------------
__global__ __launch_bounds__(256) void combine_kernel(float* __restrict__ out) {
    int t = blockIdx.x;
    int s0 = g_slot[t][0], s1 = g_slot[t][1];
    const float4* y0 = reinterpret_cast<const float4*>(g_y + (size_t)s0 * H_DIM);
    const float4* y1 = reinterpret_cast<const float4*>(g_y + (size_t)s1 * H_DIM);
    float4* o = reinterpret_cast<float4*>(out + (size_t)t * H_DIM);
    int c = threadIdx.x;
    float4 a = y0[c], b = y1[c];
    o[c] = make_float4(a.x + b.x, a.y + b.y, a.z + b.z, a.w + b.w);
}

// ---------------- launch ----------------
extern "C" void kernel_launch(void* const* d_in, const int* in_sizes, int n_in,
                              void* d_out, int out_size) {
    const float* hs = (const float*)d_in[0];   // [T, H]
    const float* gw = (const float*)d_in[1];   // [H, E]
    const float* wg = (const float*)d_in[2];   // [E, H, I]
    const float* wu = (const float*)d_in[3];   // [E, H, I]
    const float* wd = (const float*)d_in[4];   // [E, I, H]
    float* out = (float*)d_out;                // [T, H]

    static bool attr_done = false;
    if (!attr_done) {
        cudaFuncSetAttribute(gemm1_kernel, cudaFuncAttributeMaxDynamicSharedMemorySize, 73728);
        cudaFuncSetAttribute(gemm2_kernel, cudaFuncAttributeMaxDynamicSharedMemorySize, 73728);
        attr_done = true;
    }

    zero_counts_kernel<<<1, 32>>>();
    router_kernel<<<T_TOK, 128>>>(hs, gw);
    gather_x_kernel<<<dim3(E_NUM, T_TOK / 8), 256>>>(hs);
    pack_w1_kernel<<<dim3(32, 16, E_NUM), 512>>>(wg, wu);
    pack_w2_kernel<<<dim3(64, 4, E_NUM), 512>>>(wd);

    dim3 g1(T_TOK / 128, E_NUM, I_DIM / 128);   // (16, 8, 16)
    gemm1_kernel<<<g1, 512, 73728>>>();

    dim3 g2(T_TOK / 128, E_NUM, H_DIM / 256);   // (16, 8, 4)
    gemm2_kernel<<<g2, 512, 73728>>>();

    combine_kernel<<<T_TOK, 256>>>(out);
}

// round 15
// speedup vs baseline: 1.5308x; 1.0951x over previous
#include <cuda_runtime.h>
#include <cuda_fp16.h>
#include <math.h>
#include <stdint.h>

#define T_TOK 2048
#define H_DIM 1024
#define E_NUM 8
#define I_DIM 2048

// ---------------- device scratch ----------------
__device__ int      g_count[E_NUM];
__device__ int      g_tok[E_NUM][T_TOK];
__device__ float    g_wt[E_NUM][T_TOK];
__device__ int      g_slot[T_TOK][2];
// Pre-packed operand images (exact smem layouts, fp16 words):
__device__ uint32_t g_x16A[(size_t)E_NUM * 16 * 32 * 2048];  // 32 MB: gemm1 A tiles
__device__ uint32_t g_w1[(size_t)E_NUM * 16 * 32 * 4096];    // 64 MB: gemm1 B tiles (wg/wu interleaved)
__device__ uint32_t g_w2[(size_t)E_NUM * 4 * 64 * 4096];     // 32 MB: gemm2 B tiles (wd)
__device__ uint32_t g_actF[(size_t)E_NUM * 16 * 64 * 2048];  // 64 MB: gemm2 A tiles (act, fragment layout)
__device__ float    g_y[(size_t)E_NUM * T_TOK * H_DIM];      // 64 MB

// ---------------- helpers ----------------
__device__ __forceinline__ uint32_t f2h2(float lo, float hi) {
    __half2 h;
    h.x = __float2half_rn(lo);
    h.y = __float2half_rn(hi);
    return *reinterpret_cast<uint32_t*>(&h);
}
__device__ __forceinline__ void mma_f16(float* c, const uint32_t* a, const uint32_t* b) {
    asm volatile(
        "mma.sync.aligned.m16n8k16.row.col.f32.f16.f16.f32 "
        "{%0,%1,%2,%3}, {%4,%5,%6,%7}, {%8,%9}, {%0,%1,%2,%3};"
        : "+f"(c[0]), "+f"(c[1]), "+f"(c[2]), "+f"(c[3])
        : "r"(a[0]), "r"(a[1]), "r"(a[2]), "r"(a[3]), "r"(b[0]), "r"(b[1]));
}
#define CP_ASYNC16(smem_u32, gptr) \
    asm volatile("cp.async.cg.shared.global [%0], [%1], 16;" :: "r"(smem_u32), "l"(gptr) : "memory")
#define CP_COMMIT() asm volatile("cp.async.commit_group;" ::: "memory")
#define CP_WAIT2()  asm volatile("cp.async.wait_group 2;" ::: "memory")

// A-fragment word index for (m in [0,128), k2 in [0,16)) — validated mapping.
__device__ __forceinline__ int a_word_idx(int m, int k2) {
    int ks = k2 >> 3;
    int reg = ((k2 & 4) >> 1) + ((m & 8) >> 3);
    int lane0 = ((m & 7) << 2) + (k2 & 3);
    return (((ks * 8 + (m >> 4)) * 32) + lane0) * 4 + reg;
}

// ---------------- small kernels ----------------
__global__ void zero_counts_kernel() {
    if (threadIdx.x < E_NUM) g_count[threadIdx.x] = 0;
}

__global__ void router_kernel(const float* __restrict__ hs, const float* __restrict__ gw) {
    int t = blockIdx.x;
    const float* x = hs + (size_t)t * H_DIM;
    float acc[E_NUM];
#pragma unroll
    for (int e = 0; e < E_NUM; e++) acc[e] = 0.f;
    for (int j = threadIdx.x; j < H_DIM; j += blockDim.x) {
        float xv = x[j];
        const float4* grow = reinterpret_cast<const float4*>(gw + (size_t)j * E_NUM);
        float4 g0 = grow[0], g1 = grow[1];
        acc[0] += xv * g0.x; acc[1] += xv * g0.y; acc[2] += xv * g0.z; acc[3] += xv * g0.w;
        acc[4] += xv * g1.x; acc[5] += xv * g1.y; acc[6] += xv * g1.z; acc[7] += xv * g1.w;
    }
#pragma unroll
    for (int off = 16; off > 0; off >>= 1)
#pragma unroll
        for (int e = 0; e < E_NUM; e++)
            acc[e] += __shfl_xor_sync(0xffffffffu, acc[e], off);
    __shared__ float s[4][E_NUM];
    int warp = threadIdx.x >> 5, lane = threadIdx.x & 31;
    if (lane == 0)
#pragma unroll
        for (int e = 0; e < E_NUM; e++) s[warp][e] = acc[e];
    __syncthreads();
    if (threadIdx.x == 0) {
        float l[E_NUM];
#pragma unroll
        for (int e = 0; e < E_NUM; e++)
            l[e] = tanhf((s[0][e] + s[1][e] + s[2][e] + s[3][e]) * (1.0f / 30.0f));
        int i0 = 0;
#pragma unroll
        for (int e = 1; e < E_NUM; e++) if (l[e] > l[i0]) i0 = e;
        int i1 = (i0 == 0) ? 1 : 0;
#pragma unroll
        for (int e = 0; e < E_NUM; e++) if (e != i0 && l[e] > l[i1]) i1 = e;
        float d  = l[i1] - l[i0];
        float ed = expf(d);
        float inv = 1.0f / (1.0f + ed);
        float p0 = inv, p1 = ed * inv;
        int p = atomicAdd(&g_count[i0], 1);
        g_tok[i0][p] = t; g_wt[i0][p] = p0; g_slot[t][0] = i0 * T_TOK + p;
        p = atomicAdd(&g_count[i1], 1);
        g_tok[i1][p] = t; g_wt[i1][p] = p1; g_slot[t][1] = i1 * T_TOK + p;
    }
}

// gather hs rows into fp16 A-fragment tile images (zero-fill pad slots)
__global__ __launch_bounds__(256) void gather_x_kernel(const float* __restrict__ hs) {
    int e = blockIdx.x;
    int count = g_count[e];
    int s = blockIdx.y * 8 + (threadIdx.x >> 5);
    int lane = threadIdx.x & 31;
    int mblk = s >> 7, ml = s & 127;
    uint32_t* base = g_x16A + ((size_t)(e * 16 + mblk)) * 32 * 2048;
    if (s < count) {
        int tok = g_tok[e][s];
        const float2* src = reinterpret_cast<const float2*>(hs + (size_t)tok * H_DIM);
#pragma unroll
        for (int i = 0; i < 16; ++i) {
            int w = lane + i * 32;                 // global k2 index, 0..511
            float2 v = src[w];
            base[(size_t)(w >> 4) * 2048 + a_word_idx(ml, w & 15)] = f2h2(v.x, v.y);
        }
    } else {
#pragma unroll
        for (int i = 0; i < 16; ++i) {
            int w = lane + i * 32;
            base[(size_t)(w >> 4) * 2048 + a_word_idx(ml, w & 15)] = 0u;
        }
    }
}

// pack wg/wu into gemm1 B tiles — body replicates the validated staged-B code
__global__ __launch_bounds__(512) void pack_w1_kernel(const float* __restrict__ wg,
                                                      const float* __restrict__ wu) {
    const int chunk = blockIdx.x, nblk = blockIdx.y, e = blockIdx.z;
    const float* wgp = wg + (size_t)e * H_DIM * I_DIM + nblk * 128;
    const float* wup = wu + (size_t)e * H_DIM * I_DIM + nblk * 128;
    uint32_t* tile = g_w1 + (((size_t)(e * 16 + nblk)) * 32 + chunk) * 4096;
    const int k0 = chunk * 32, tid = threadIdx.x;
#pragma unroll
    for (int it = 0; it < 2; ++it) {
        int f = tid + it * 512;
        int n4 = f & 63, k2 = f >> 6;
        int blk = n4 >> 1;
        const float* bsrc = (blk & 1) ? wup : wgp;
        int srcoff = (blk >> 1) * 8 + (n4 & 1) * 4;
        float4 r0 = *reinterpret_cast<const float4*>(bsrc + (size_t)(k0 + 2 * k2) * I_DIM + srcoff);
        float4 r1 = *reinterpret_cast<const float4*>(bsrc + (size_t)(k0 + 2 * k2 + 1) * I_DIM + srcoff);
        int pn4 = n4 ^ ((k2 & 3) << 1);
        *reinterpret_cast<uint4*>(tile + k2 * 256 + pn4 * 4) =
            make_uint4(f2h2(r0.x, r1.x), f2h2(r0.y, r1.y), f2h2(r0.z, r1.z), f2h2(r0.w, r1.w));
    }
}

// pack wd into gemm2 B tiles
__global__ __launch_bounds__(512) void pack_w2_kernel(const float* __restrict__ wd) {
    const int chunk = blockIdx.x, nblk = blockIdx.y, e = blockIdx.z;
    const float* wdp = wd + (size_t)e * I_DIM * H_DIM + nblk * 256;
    uint32_t* tile = g_w2 + (((size_t)(e * 4 + nblk)) * 64 + chunk) * 4096;
    const int k0 = chunk * 32, tid = threadIdx.x;
#pragma unroll
    for (int it = 0; it < 2; ++it) {
        int f = tid + it * 512;
        int n4 = f & 63, k2 = f >> 6;
        float4 r0 = *reinterpret_cast<const float4*>(wdp + (size_t)(k0 + 2 * k2) * H_DIM + n4 * 4);
        float4 r1 = *reinterpret_cast<const float4*>(wdp + (size_t)(k0 + 2 * k2 + 1) * H_DIM + n4 * 4);
        int pn4 = n4 ^ ((k2 & 3) << 1);
        *reinterpret_cast<uint4*>(tile + k2 * 256 + pn4 * 4) =
            make_uint4(f2h2(r0.x, r1.x), f2h2(r0.y, r1.y), f2h2(r0.z, r1.z), f2h2(r0.w, r1.w));
    }
}

__device__ __forceinline__ float gelu_tanh(float g) {
    float c = 0.7978845608028654f * (g + 0.044715f * g * g * g);
    return 0.5f * g * (1.0f + tanhf(c));
}

// ===== fragment math: fp16 m16n8k16, warp tile 64x32, 16 warps (2m x 8n) =====
#define GX_MMA(s)                                                                     \
    {                                                                                 \
        const uint32_t* As = sm32 + (s) * 6144;                                       \
        const uint32_t* Bs = As + 2048;                                               \
        const int kl = lane & 3, dn = lane >> 2;                                      \
        _Pragma("unroll")                                                             \
        for (int ks = 0; ks < 2; ++ks) {                                              \
            uint4 af[4];                                                              \
            _Pragma("unroll")                                                         \
            for (int mt = 0; mt < 4; ++mt)                                            \
                af[mt] = *reinterpret_cast<const uint4*>(                             \
                    As + ((ks * 8 + wm * 4 + mt) * 32 + lane) * 4);                   \
            uint2 bf[4];                                                              \
            _Pragma("unroll")                                                         \
            for (int nt = 0; nt < 4; ++nt) {                                          \
                int pn = (wn * 32 + nt * 8 + dn) ^ (kl << 3);                         \
                bf[nt].x = Bs[(ks * 8 + kl) * 256 + pn];                              \
                bf[nt].y = Bs[(ks * 8 + kl + 4) * 256 + pn];                          \
            }                                                                         \
            _Pragma("unroll")                                                         \
            for (int mt = 0; mt < 4; ++mt)                                            \
                _Pragma("unroll")                                                     \
                for (int nt = 0; nt < 4; ++nt)                                        \
                    mma_f16(acc[mt][nt], (const uint32_t*)&af[mt], (const uint32_t*)&bf[nt]); \
        }                                                                             \
    }

// ============================================================================
// GEMM1: act = gelu(X@wg)*(X@wu), epilogue writes gemm2 A-fragment tiles.
// CTA M=128 x Nphys=256, 512 thr, kb=32, 3-stage, full cp.async staging.
// Grid: x = mblk (fastest), y = e, z = nblk (slowest).
// ============================================================================
__global__ __launch_bounds__(512, 1)
void gemm1_kernel() {
    const int e = blockIdx.y;
    const int count = g_count[e];
    const int m0 = blockIdx.x * 128;
    if (m0 >= count) return;
    const int n0 = blockIdx.z * 128;

    extern __shared__ uint32_t sm32[];
    const uint32_t sbase = (uint32_t)__cvta_generic_to_shared(sm32);

    const int tid = threadIdx.x, wid = tid >> 5, lane = tid & 31;
    const int wm = wid & 1, wn = wid >> 1;

    const uint4* At = reinterpret_cast<const uint4*>(
        g_x16A + ((size_t)(e * 16 + blockIdx.x)) * 32 * 2048);
    const uint4* Bt = reinterpret_cast<const uint4*>(
        g_w1 + ((size_t)(e * 16 + blockIdx.z)) * 32 * 4096);

    float acc[4][4][4];
#pragma unroll
    for (int i = 0; i < 4; i++)
#pragma unroll
        for (int j = 0; j < 4; j++)
#pragma unroll
            for (int q = 0; q < 4; q++) acc[i][j][q] = 0.f;

#define G1_ISSUE(s, c)                                                                \
    {                                                                                 \
        CP_ASYNC16(sbase + ((s) * 6144 + tid * 4) * 4, At + (size_t)(c) * 512 + tid); \
        CP_ASYNC16(sbase + ((s) * 6144 + 2048 + tid * 4) * 4,                         \
                   Bt + (size_t)(c) * 1024 + tid);                                    \
        CP_ASYNC16(sbase + ((s) * 6144 + 4096 + tid * 4) * 4,                         \
                   Bt + (size_t)(c) * 1024 + 512 + tid);                              \
    }

    const int NC = 32;
    G1_ISSUE(0, 0); CP_COMMIT();
    G1_ISSUE(1, 1); CP_COMMIT();
    for (int c = 0; c < NC; ++c) {
        if (c + 2 < NC) G1_ISSUE((c + 2) % 3, c + 2);
        CP_COMMIT();
        CP_WAIT2();
        __syncthreads();
        GX_MMA(c % 3);
        __syncthreads();
    }
#undef G1_ISSUE

    // ---- epilogue: (acc[mt][2j], acc[mt][2j+1]) = (g,u);
    //      write fp16 act directly into gemm2 A-fragment tile layout ----
    uint32_t* actT = g_actF + ((size_t)(e * 16 + blockIdx.x)) * 64 * 2048;
#pragma unroll
    for (int mt = 0; mt < 4; ++mt) {
        int row_base = wm * 64 + mt * 16 + (lane >> 2);
#pragma unroll
        for (int h = 0; h < 2; ++h) {
            int mrow = row_base + h * 8;
            int gpos = m0 + mrow;
            if (gpos >= count) continue;
#pragma unroll
            for (int j = 0; j < 2; ++j) {
                int col = n0 + (2 * wn + j) * 8 + (lane & 3) * 2;
                int k2 = col >> 1;
                uint32_t w = f2h2(
                    gelu_tanh(acc[mt][2 * j][2 * h])     * acc[mt][2 * j + 1][2 * h],
                    gelu_tanh(acc[mt][2 * j][2 * h + 1]) * acc[mt][2 * j + 1][2 * h + 1]);
                actT[(size_t)(k2 >> 4) * 2048 + a_word_idx(mrow, k2 & 15)] = w;
            }
        }
    }
}

// ============================================================================
// GEMM2: y = weight * (act @ wd). Fully cp.async from packed tiles.
// CTA 128x256, 512 thr, kb=32, 3-stage. Grid: x=mblk, y=e, z=nblk.
// Pad A rows (gpos >= count) may hold garbage: they only affect pad outputs,
// which the guarded epilogue never writes.
// ============================================================================
__global__ __launch_bounds__(512, 1)
void gemm2_kernel() {
    const int e = blockIdx.y;
    const int count = g_count[e];
    const int m0 = blockIdx.x * 128;
    if (m0 >= count) return;
    const int n0 = blockIdx.z * 256;

    extern __shared__ uint32_t sm32[];
    const uint32_t sbase = (uint32_t)__cvta_generic_to_shared(sm32);

    const int tid = threadIdx.x, wid = tid >> 5, lane = tid & 31;
    const int wm = wid & 1, wn = wid >> 1;

    const uint4* At = reinterpret_cast<const uint4*>(
        g_actF + ((size_t)(e * 16 + blockIdx.x)) * 64 * 2048);
    const uint4* Bt = reinterpret_cast<const uint4*>(
        g_w2 + ((size_t)(e * 4 + blockIdx.z)) * 64 * 4096);

    float acc[4][4][4];
#pragma unroll
    for (int i = 0; i < 4; i++)
#pragma unroll
        for (int j = 0; j < 4; j++)
#pragma unroll
            for (int q = 0; q < 4; q++) acc[i][j][q] = 0.f;

#define G2_ISSUE(s, c)                                                                \
    {                                                                                 \
        CP_ASYNC16(sbase + ((s) * 6144 + tid * 4) * 4, At + (size_t)(c) * 512 + tid); \
        CP_ASYNC16(sbase + ((s) * 6144 + 2048 + tid * 4) * 4,                         \
                   Bt + (size_t)(c) * 1024 + tid);                                    \
        CP_ASYNC16(sbase + ((s) * 6144 + 4096 + tid * 4) * 4,                         \
                   Bt + (size_t)(c) * 1024 + 512 + tid);                              \
    }

    const int NC = 64;
    G2_ISSUE(0, 0); CP_COMMIT();
    G2_ISSUE(1, 1); CP_COMMIT();
    for (int c = 0; c < NC; ++c) {
        if (c + 2 < NC) G2_ISSUE((c + 2) % 3, c + 2);
        CP_COMMIT();
        CP_WAIT2();
        __syncthreads();
        GX_MMA(c % 3);
        __syncthreads();
    }
#undef G2_ISSUE

    // ---- epilogue: scale by combine weight, write slot buffer ----
#pragma unroll
    for (int mt = 0; mt < 4; ++mt) {
        int row_base = wm * 64 + mt * 16 + (lane >> 2);
#pragma unroll
        for (int h = 0; h < 2; ++h) {
            int gpos = m0 + row_base + h * 8;
            if (gpos >= count) continue;
            float w = g_wt[e][gpos];
            float* dst = g_y + ((size_t)e * T_TOK + gpos) * H_DIM + n0;
#pragma unroll
            for (int nt = 0; nt < 4; ++nt) {
                int col = wn * 32 + nt * 8 + (lane & 3) * 2;
                float2 o;
                o.x = w * acc[mt][nt][2 * h];
                o.y = w * acc[mt][nt][2 * h + 1];
                *reinterpret_cast<float2*>(dst + col) = o;
            }
        }
    }
}

// ---------------- combine: out[t] = y[slot0] + y[slot1] ----------------
__global__ __launch_bounds__(256) void combine_kernel(float* __restrict__ out) {
    int t = blockIdx.x;
    int s0 = g_slot[t][0], s1 = g_slot[t][1];
    const float4* y0 = reinterpret_cast<const float4*>(g_y + (size_t)s0 * H_DIM);
    const float4* y1 = reinterpret_cast<const float4*>(g_y + (size_t)s1 * H_DIM);
    float4* o = reinterpret_cast<float4*>(out + (size_t)t * H_DIM);
    int c = threadIdx.x;
    float4 a = y0[c], b = y1[c];
    o[c] = make_float4(a.x + b.x, a.y + b.y, a.z + b.z, a.w + b.w);
}

// ---------------- launch ----------------
extern "C" void kernel_launch(void* const* d_in, const int* in_sizes, int n_in,
                              void* d_out, int out_size) {
    const float* hs = (const float*)d_in[0];   // [T, H]
    const float* gw = (const float*)d_in[1];   // [H, E]
    const float* wg = (const float*)d_in[2];   // [E, H, I]
    const float* wu = (const float*)d_in[3];   // [E, H, I]
    const float* wd = (const float*)d_in[4];   // [E, I, H]
    float* out = (float*)d_out;                // [T, H]

    static bool attr_done = false;
    if (!attr_done) {
        cudaFuncSetAttribute(gemm1_kernel, cudaFuncAttributeMaxDynamicSharedMemorySize, 73728);
        cudaFuncSetAttribute(gemm2_kernel, cudaFuncAttributeMaxDynamicSharedMemorySize, 73728);
        attr_done = true;
    }

    zero_counts_kernel<<<1, 32>>>();
    router_kernel<<<T_TOK, 128>>>(hs, gw);
    gather_x_kernel<<<dim3(E_NUM, T_TOK / 8), 256>>>(hs);
    pack_w1_kernel<<<dim3(32, 16, E_NUM), 512>>>(wg, wu);
    pack_w2_kernel<<<dim3(64, 4, E_NUM), 512>>>(wd);

    dim3 g1(T_TOK / 128, E_NUM, I_DIM / 128);   // (16, 8, 16)
    gemm1_kernel<<<g1, 512, 73728>>>();

    dim3 g2(T_TOK / 128, E_NUM, H_DIM / 256);   // (16, 8, 4)
    gemm2_kernel<<<g2, 512, 73728>>>();

    combine_kernel<<<T_TOK, 256>>>(out);
}